// round 11
// baseline (speedup 1.0000x reference)
#include <cuda_runtime.h>
#include <math.h>

#define BB  8
#define HH  8
#define SEQ 1024
#define DM  512
#define DEP 64

__device__ float g_Q[BB*HH*SEQ*DEP];
__device__ float g_K[BB*HH*SEQ*DEP];   // TRANSPOSED: [bh][d][s]
__device__ float g_V[BB*HH*SEQ*DEP];
__device__ float g_X[BB*HH*SEQ*DEP];

typedef unsigned long long ull;
__device__ __forceinline__ ull pk2(float lo, float hi) {
    ull r; asm("mov.b64 %0, {%1, %2};" : "=l"(r) : "f"(lo), "f"(hi)); return r;
}
__device__ __forceinline__ void fma2(ull& d, ull a, ull b) {
    asm("fma.rn.f32x2 %0, %1, %2, %0;" : "+l"(d) : "l"(a), "l"(b));
}
__device__ __forceinline__ float2 upk(ull v) {
    float2 f; asm("mov.b64 {%0, %1}, %2;" : "=f"(f.x), "=f"(f.y) : "l"(v)); return f;
}

// =========================================================================
// Projection GEMM. tr=0: Out[bh][s][d].  tr=1: Out[bh][d][s] (K^T).
// =========================================================================
__global__ __launch_bounds__(128)
void proj_kernel(const float* __restrict__ X, const float* __restrict__ W,
                 const float* __restrict__ bias, float* __restrict__ Out, int tr)
{
    __shared__ float As[16*132];
    __shared__ float Bs[16*68];
    const int t = threadIdx.x, tx = t & 7, ty = t >> 3;
    const int m0 = blockIdx.x * 128, h = blockIdx.y, n0 = h*64;

    ull acc[4][8];
#pragma unroll
    for (int i = 0; i < 4; i++)
#pragma unroll
        for (int c = 0; c < 8; c++) acc[i][c] = 0ull;

    for (int kk = 0; kk < DM; kk += 16) {
#pragma unroll
        for (int j = 0; j < 4; j++) {
            float4 v = *(const float4*)&X[(size_t)(m0 + t)*DM + kk + 4*j];
            As[(4*j+0)*132 + t] = v.x; As[(4*j+1)*132 + t] = v.y;
            As[(4*j+2)*132 + t] = v.z; As[(4*j+3)*132 + t] = v.w;
        }
#pragma unroll
        for (int i = 0; i < 2; i++) {
            int idx = t + 128*i, bk = idx >> 4, bc = (idx & 15)*4;
            *(float4*)&Bs[bk*68 + bc] =
                *(const float4*)&W[(size_t)(kk+bk)*DM + n0 + bc];
        }
        __syncthreads();
#pragma unroll
        for (int k = 0; k < 16; k++) {
            ulonglong2 apA = *(const ulonglong2*)&As[k*132 + ty*8];
            ulonglong2 apB = *(const ulonglong2*)&As[k*132 + ty*8 + 4];
            float4 blo = *(const float4*)&Bs[k*68 + tx*4];
            float4 bhi = *(const float4*)&Bs[k*68 + 32 + tx*4];
            float bf[8] = {blo.x,blo.y,blo.z,blo.w,bhi.x,bhi.y,bhi.z,bhi.w};
#pragma unroll
            for (int c = 0; c < 8; c++) {
                ull bd = pk2(bf[c], bf[c]);
                fma2(acc[0][c], apA.x, bd); fma2(acc[1][c], apA.y, bd);
                fma2(acc[2][c], apB.x, bd); fma2(acc[3][c], apB.y, bd);
            }
        }
        __syncthreads();
    }

    float bf2[8];
    {
        float4 u = *(const float4*)&bias[n0 + tx*4];
        float4 v = *(const float4*)&bias[n0 + 32 + tx*4];
        bf2[0]=u.x; bf2[1]=u.y; bf2[2]=u.z; bf2[3]=u.w;
        bf2[4]=v.x; bf2[5]=v.y; bf2[6]=v.z; bf2[7]=v.w;
    }
    float vr[8][8];
#pragma unroll
    for (int rp = 0; rp < 4; rp++)
#pragma unroll
        for (int c = 0; c < 8; c++) {
            float2 f = upk(acc[rp][c]);
            vr[2*rp][c] = f.x + bf2[c]; vr[2*rp+1][c] = f.y + bf2[c];
        }

    const int bh = (m0 >> 10)*HH + h;
    const int s0 = (m0 & 1023) + ty*8;
    if (!tr) {
#pragma unroll
        for (int s8 = 0; s8 < 8; s8++) {
            float* dst = &Out[((size_t)bh*SEQ + s0 + s8)*DEP];
            *(float4*)&dst[tx*4] = make_float4(vr[s8][0],vr[s8][1],vr[s8][2],vr[s8][3]);
            *(float4*)&dst[32+tx*4] = make_float4(vr[s8][4],vr[s8][5],vr[s8][6],vr[s8][7]);
        }
    } else {
#pragma unroll
        for (int c = 0; c < 8; c++) {
            int d = (c < 4) ? (tx*4 + c) : (32 + tx*4 + c - 4);
            float* dst = &Out[((size_t)bh*DEP + d)*SEQ + s0];
            *(float4*)&dst[0] = make_float4(vr[0][c],vr[1][c],vr[2][c],vr[3][c]);
            *(float4*)&dst[4] = make_float4(vr[4][c],vr[5][c],vr[6][c],vr[7][c]);
        }
    }
}

// =========================================================================
// Output GEMM: out[m,n] = Xgather[m,:] @ wo + bo.
// =========================================================================
__global__ __launch_bounds__(128)
void outproj_kernel(const float* __restrict__ W, const float* __restrict__ bias,
                    float* __restrict__ Out)
{
    __shared__ float As[16*132];
    __shared__ float Bs[16*68];
    const int t = threadIdx.x, tx = t & 7, ty = t >> 3;
    const int m0 = blockIdx.x * 128, n0 = blockIdx.y * 64;

    ull acc[4][8];
#pragma unroll
    for (int i = 0; i < 4; i++)
#pragma unroll
        for (int c = 0; c < 8; c++) acc[i][c] = 0ull;

    const int mA = m0 + t, bbA = mA >> 10, sA = mA & 1023;

    for (int kk = 0; kk < DM; kk += 16) {
#pragma unroll
        for (int j = 0; j < 4; j++) {
            int kb = kk + 4*j, hs = kb >> 6, dd = kb & 63;
            float4 v = *(const float4*)
                &g_X[(((size_t)bbA*HH + hs)*SEQ + sA)*DEP + dd];
            As[(4*j+0)*132 + t] = v.x; As[(4*j+1)*132 + t] = v.y;
            As[(4*j+2)*132 + t] = v.z; As[(4*j+3)*132 + t] = v.w;
        }
#pragma unroll
        for (int i = 0; i < 2; i++) {
            int idx = t + 128*i, bk = idx >> 4, bc = (idx & 15)*4;
            *(float4*)&Bs[bk*68 + bc] =
                *(const float4*)&W[(size_t)(kk+bk)*DM + n0 + bc];
        }
        __syncthreads();
#pragma unroll
        for (int k = 0; k < 16; k++) {
            ulonglong2 apA = *(const ulonglong2*)&As[k*132 + ty*8];
            ulonglong2 apB = *(const ulonglong2*)&As[k*132 + ty*8 + 4];
            float4 blo = *(const float4*)&Bs[k*68 + tx*4];
            float4 bhi = *(const float4*)&Bs[k*68 + 32 + tx*4];
            float bf[8] = {blo.x,blo.y,blo.z,blo.w,bhi.x,bhi.y,bhi.z,bhi.w};
#pragma unroll
            for (int c = 0; c < 8; c++) {
                ull bd = pk2(bf[c], bf[c]);
                fma2(acc[0][c], apA.x, bd); fma2(acc[1][c], apA.y, bd);
                fma2(acc[2][c], apB.x, bd); fma2(acc[3][c], apB.y, bd);
            }
        }
        __syncthreads();
    }

    float4 blo4 = *(const float4*)&bias[n0 + tx*4];
    float4 bhi4 = *(const float4*)&bias[n0 + 32 + tx*4];
#pragma unroll
    for (int rp = 0; rp < 4; rp++) {
        float2 fx[8];
#pragma unroll
        for (int c = 0; c < 8; c++) fx[c] = upk(acc[rp][c]);
#pragma unroll
        for (int e = 0; e < 2; e++) {
            int m = m0 + ty*8 + 2*rp + e;
            float a0=e?fx[0].y:fx[0].x, a1=e?fx[1].y:fx[1].x;
            float a2=e?fx[2].y:fx[2].x, a3=e?fx[3].y:fx[3].x;
            float a4=e?fx[4].y:fx[4].x, a5=e?fx[5].y:fx[5].x;
            float a6=e?fx[6].y:fx[6].x, a7=e?fx[7].y:fx[7].x;
            *(float4*)&Out[(size_t)m*DM + n0 + tx*4] =
                make_float4(a0+blo4.x, a1+blo4.y, a2+blo4.z, a3+blo4.w);
            *(float4*)&Out[(size_t)m*DM + n0 + 32 + tx*4] =
                make_float4(a4+bhi4.x, a5+bhi4.y, a6+bhi4.z, a7+bhi4.w);
        }
    }
}

// =========================================================================
// Attention: CTA per (b,h,16-q tile), 8 warps; warp w owns k in [128w,128w+128).
// Scores register-resident; exp IN PLACE (no spills); pipelined K/V loads.
// =========================================================================
#define OFF_QPP 16384
#define OFF_PAR (16384 + 1024)
#define OFF_SUM (OFF_PAR + 8192)
#define ATTN_SMEM_BYTES ((OFF_SUM + 128) * 4)

__global__ __launch_bounds__(256, 2)
void attn_kernel(const float* __restrict__ mask, const float* __restrict__ aw,
                 float* __restrict__ attn_out)
{
    extern __shared__ float sm[];
    float* SsT  = sm;
    ull*   Qpp  = (ull*)(sm + OFF_QPP);
    float* Par  = sm + OFF_PAR;
    float* SumB = sm + OFF_SUM;

    const int t = threadIdx.x, w = t >> 5, l = t & 31;
    const int qt = blockIdx.x, h = blockIdx.y, b = blockIdx.z;
    const int bh = b*HH + h, q0 = qt*16, k0 = w*128;

    const float* Qg  = g_Q + ((size_t)bh*SEQ + q0)*DEP;
    const float* KTg = g_K + (size_t)bh*DEP*SEQ;
    const float* Vg  = g_V + (size_t)bh*SEQ*DEP;

#pragma unroll
    for (int i = 0; i < 2; i++) {
        int idx = t + 256*i, d = idx >> 3, qp = idx & 7;
        Qpp[idx] = pk2(Qg[(2*qp)*DEP + d], Qg[(2*qp+1)*DEP + d]);
    }
    __syncthreads();

    // ---- phase 1: scores, pipelined K loads -----------------------------
    ull acc[4][8];
#pragma unroll
    for (int j = 0; j < 4; j++)
#pragma unroll
        for (int qp = 0; qp < 8; qp++) acc[j][qp] = 0ull;

    float kv[4];
#pragma unroll
    for (int j = 0; j < 4; j++)
        kv[j] = __ldg(&KTg[k0 + 32*j + l]);

#pragma unroll 4
    for (int d = 0; d < DEP; d++) {
        float kvn[4];
        if (d + 1 < DEP) {
#pragma unroll
            for (int j = 0; j < 4; j++)
                kvn[j] = __ldg(&KTg[(size_t)(d+1)*SEQ + k0 + 32*j + l]);
        }
        ulonglong2 qA = *(const ulonglong2*)&Qpp[d*8];
        ulonglong2 qB = *(const ulonglong2*)&Qpp[d*8 + 2];
        ulonglong2 qC = *(const ulonglong2*)&Qpp[d*8 + 4];
        ulonglong2 qD = *(const ulonglong2*)&Qpp[d*8 + 6];
#pragma unroll
        for (int j = 0; j < 4; j++) {
            ull kd = pk2(kv[j], kv[j]);
            fma2(acc[j][0], kd, qA.x); fma2(acc[j][1], kd, qA.y);
            fma2(acc[j][2], kd, qB.x); fma2(acc[j][3], kd, qB.y);
            fma2(acc[j][4], kd, qC.x); fma2(acc[j][5], kd, qC.y);
            fma2(acc[j][6], kd, qD.x); fma2(acc[j][7], kd, qD.y);
        }
#pragma unroll
        for (int j = 0; j < 4; j++) kv[j] = kvn[j];
    }

    // ---- exp IN PLACE (mask+scale folded), then row sums ----------------
#pragma unroll
    for (int j = 0; j < 4; j++) {
        float mb = -1.0e9f * __ldg(&mask[(size_t)b*SEQ + k0 + 32*j + l]);
#pragma unroll
        for (int qp = 0; qp < 8; qp++) {
            float2 f = upk(acc[j][qp]);
            acc[j][qp] = pk2(__expf(fmaf(f.x, 0.125f, mb)),
                             __expf(fmaf(f.y, 0.125f, mb)));
        }
    }
    {
        float sq[16];
#pragma unroll
        for (int qp = 0; qp < 8; qp++) {
            float2 f0 = upk(acc[0][qp]), f1 = upk(acc[1][qp]);
            float2 f2 = upk(acc[2][qp]), f3 = upk(acc[3][qp]);
            sq[2*qp]   = (f0.x + f1.x) + (f2.x + f3.x);
            sq[2*qp+1] = (f0.y + f1.y) + (f2.y + f3.y);
        }
#pragma unroll
        for (int off = 16; off > 0; off >>= 1)
#pragma unroll
            for (int q = 0; q < 16; q++)
                sq[q] += __shfl_xor_sync(0xffffffffu, sq[q], off);
        if (l < 16) SumB[w*16 + l] = sq[l];
    }
    __syncthreads();

    float inv[16];
#pragma unroll
    for (int q = 0; q < 16; q++) {
        float s = 0.f;
#pragma unroll
        for (int ww = 0; ww < 8; ww++) s += SumB[ww*16 + q];
        inv[q] = 1.0f / s;
    }

    // ---- normalize * aw -> attn gmem + swizzled SsT ---------------------
#pragma unroll
    for (int j = 0; j < 4; j++) {
        int k = k0 + 32*j + l;
        float a[16];
#pragma unroll
        for (int qp = 0; qp < 8; qp++) {
            float2 f = upk(acc[j][qp]);
            a[2*qp]   = f.x * inv[2*qp] *
                        __ldg(&aw[((size_t)b*SEQ + q0 + 2*qp)*SEQ + k]);
            a[2*qp+1] = f.y * inv[2*qp+1] *
                        __ldg(&aw[((size_t)b*SEQ + q0 + 2*qp + 1)*SEQ + k]);
        }
#pragma unroll
        for (int q = 0; q < 16; q++)
            attn_out[((size_t)bh*SEQ + q0 + q)*SEQ + k] = a[q];
        int sw = (k >> 1) & 3;
#pragma unroll
        for (int c = 0; c < 4; c++)
            *(float4*)&SsT[k*16 + 4*(c ^ sw)] =
                make_float4(a[4*c], a[4*c+1], a[4*c+2], a[4*c+3]);
    }
    __syncthreads();

    // ---- phase 2: partial X = A @ V, pipelined V loads ------------------
    ull x[8][2];
#pragma unroll
    for (int qp = 0; qp < 8; qp++) { x[qp][0] = 0ull; x[qp][1] = 0ull; }

    float v0 = __ldg(&Vg[(size_t)k0*DEP + l]);
    float v1 = __ldg(&Vg[(size_t)k0*DEP + l + 32]);

#pragma unroll 4
    for (int ki = 0; ki < 128; ki++) {
        float n0 = 0.f, n1 = 0.f;
        if (ki + 1 < 128) {
            n0 = __ldg(&Vg[(size_t)(k0 + ki + 1)*DEP + l]);
            n1 = __ldg(&Vg[(size_t)(k0 + ki + 1)*DEP + l + 32]);
        }
        int k = k0 + ki;
        ull vd0 = pk2(v0, v0), vd1 = pk2(v1, v1);
        int sw = (k >> 1) & 3;
        const ulonglong2* row = (const ulonglong2*)&SsT[k*16];
#pragma unroll
        for (int p = 0; p < 4; p++) {
            ulonglong2 u = row[p];
            int c = p ^ sw;
            fma2(x[2*c][0],   u.x, vd0); fma2(x[2*c][1],   u.x, vd1);
            fma2(x[2*c+1][0], u.y, vd0); fma2(x[2*c+1][1], u.y, vd1);
        }
        v0 = n0; v1 = n1;
    }
    __syncthreads();

#pragma unroll
    for (int qp = 0; qp < 8; qp++) {
        float2 f0 = upk(x[qp][0]), f1 = upk(x[qp][1]);
        Par[(w*16 + 2*qp)*64 + l]          = f0.x;
        Par[(w*16 + 2*qp + 1)*64 + l]      = f0.y;
        Par[(w*16 + 2*qp)*64 + l + 32]     = f1.x;
        Par[(w*16 + 2*qp + 1)*64 + l + 32] = f1.y;
    }
    __syncthreads();

    {
        int q = t >> 4, c4 = (t & 15)*4;
        float4 s = make_float4(0.f, 0.f, 0.f, 0.f);
#pragma unroll
        for (int ww = 0; ww < 8; ww++) {
            float4 u = *(float4*)&Par[(ww*16 + q)*64 + c4];
            s.x += u.x; s.y += u.y; s.z += u.z; s.w += u.w;
        }
        *(float4*)&g_X[((size_t)bh*SEQ + q0 + q)*DEP + c4] = s;
    }
}

// =========================================================================
extern "C" void kernel_launch(void* const* d_in, const int* in_sizes, int n_in,
                              void* d_out, int out_size)
{
    const float* q_in = (const float*)d_in[0];
    const float* k_in = (const float*)d_in[1];
    const float* v_in = (const float*)d_in[2];
    const float* mask = (const float*)d_in[3];
    const float* aw   = (const float*)d_in[4];
    const float* wq   = (const float*)d_in[5];
    const float* bq   = (const float*)d_in[6];
    const float* wk   = (const float*)d_in[7];
    const float* bk   = (const float*)d_in[8];
    const float* wv   = (const float*)d_in[9];
    const float* bv   = (const float*)d_in[10];
    const float* wo   = (const float*)d_in[11];
    const float* bo   = (const float*)d_in[12];

    float* out      = (float*)d_out;                // [B,S,512]
    float* attn_out = out + (size_t)BB*SEQ*DM;      // [B,H,S,S]

    float *Qp, *Kp, *Vp;
    cudaGetSymbolAddress((void**)&Qp, g_Q);
    cudaGetSymbolAddress((void**)&Kp, g_K);
    cudaGetSymbolAddress((void**)&Vp, g_V);

    dim3 gproj(64, 8);
    proj_kernel<<<gproj, 128>>>(q_in, wq, bq, Qp, 0);
    proj_kernel<<<gproj, 128>>>(k_in, wk, bk, Kp, 1);   // K transposed
    proj_kernel<<<gproj, 128>>>(v_in, wv, bv, Vp, 0);

    cudaFuncSetAttribute(attn_kernel,
                         cudaFuncAttributeMaxDynamicSharedMemorySize,
                         ATTN_SMEM_BYTES);
    attn_kernel<<<dim3(64, 8, 8), 256, ATTN_SMEM_BYTES>>>(mask, aw, attn_out);

    outproj_kernel<<<dim3(64, 8), 128>>>(wo, bo, out);
}

// round 12
// speedup vs baseline: 2.2703x; 2.2703x over previous
#include <cuda_runtime.h>
#include <math.h>

#define BB  8
#define HH  8
#define SEQ 1024
#define DM  512
#define DEP 64

__device__ float g_Q[BB*HH*SEQ*DEP];
__device__ float g_K[BB*HH*SEQ*DEP];   // TRANSPOSED: [bh][d][s]
__device__ float g_V[BB*HH*SEQ*DEP];
__device__ float g_X[BB*HH*SEQ*DEP];

typedef unsigned long long ull;
__device__ __forceinline__ ull pk2(float lo, float hi) {
    ull r; asm("mov.b64 %0, {%1, %2};" : "=l"(r) : "f"(lo), "f"(hi)); return r;
}
__device__ __forceinline__ void fma2(ull& d, ull a, ull b) {
    asm("fma.rn.f32x2 %0, %1, %2, %0;" : "+l"(d) : "l"(a), "l"(b));
}
__device__ __forceinline__ float2 upk(ull v) {
    float2 f; asm("mov.b64 {%0, %1}, %2;" : "=f"(f.x), "=f"(f.y) : "l"(v)); return f;
}

// =========================================================================
// Projection GEMM. tr=0: Out[bh][s][d].  tr=1: Out[bh][d][s] (K^T).
// =========================================================================
__global__ __launch_bounds__(128)
void proj_kernel(const float* __restrict__ X, const float* __restrict__ W,
                 const float* __restrict__ bias, float* __restrict__ Out, int tr)
{
    __shared__ float As[16*132];
    __shared__ float Bs[16*68];
    const int t = threadIdx.x, tx = t & 7, ty = t >> 3;
    const int m0 = blockIdx.x * 128, h = blockIdx.y, n0 = h*64;

    ull acc[4][8];
#pragma unroll
    for (int i = 0; i < 4; i++)
#pragma unroll
        for (int c = 0; c < 8; c++) acc[i][c] = 0ull;

    for (int kk = 0; kk < DM; kk += 16) {
#pragma unroll
        for (int j = 0; j < 4; j++) {
            float4 v = *(const float4*)&X[(size_t)(m0 + t)*DM + kk + 4*j];
            As[(4*j+0)*132 + t] = v.x; As[(4*j+1)*132 + t] = v.y;
            As[(4*j+2)*132 + t] = v.z; As[(4*j+3)*132 + t] = v.w;
        }
#pragma unroll
        for (int i = 0; i < 2; i++) {
            int idx = t + 128*i, bk = idx >> 4, bc = (idx & 15)*4;
            *(float4*)&Bs[bk*68 + bc] =
                *(const float4*)&W[(size_t)(kk+bk)*DM + n0 + bc];
        }
        __syncthreads();
#pragma unroll
        for (int k = 0; k < 16; k++) {
            ulonglong2 apA = *(const ulonglong2*)&As[k*132 + ty*8];
            ulonglong2 apB = *(const ulonglong2*)&As[k*132 + ty*8 + 4];
            float4 blo = *(const float4*)&Bs[k*68 + tx*4];
            float4 bhi = *(const float4*)&Bs[k*68 + 32 + tx*4];
            float bf[8] = {blo.x,blo.y,blo.z,blo.w,bhi.x,bhi.y,bhi.z,bhi.w};
#pragma unroll
            for (int c = 0; c < 8; c++) {
                ull bd = pk2(bf[c], bf[c]);
                fma2(acc[0][c], apA.x, bd); fma2(acc[1][c], apA.y, bd);
                fma2(acc[2][c], apB.x, bd); fma2(acc[3][c], apB.y, bd);
            }
        }
        __syncthreads();
    }

    float bf2[8];
    {
        float4 u = *(const float4*)&bias[n0 + tx*4];
        float4 v = *(const float4*)&bias[n0 + 32 + tx*4];
        bf2[0]=u.x; bf2[1]=u.y; bf2[2]=u.z; bf2[3]=u.w;
        bf2[4]=v.x; bf2[5]=v.y; bf2[6]=v.z; bf2[7]=v.w;
    }
    float vr[8][8];
#pragma unroll
    for (int rp = 0; rp < 4; rp++)
#pragma unroll
        for (int c = 0; c < 8; c++) {
            float2 f = upk(acc[rp][c]);
            vr[2*rp][c] = f.x + bf2[c]; vr[2*rp+1][c] = f.y + bf2[c];
        }

    const int bh = (m0 >> 10)*HH + h;
    const int s0 = (m0 & 1023) + ty*8;
    if (!tr) {
#pragma unroll
        for (int s8 = 0; s8 < 8; s8++) {
            float* dst = &Out[((size_t)bh*SEQ + s0 + s8)*DEP];
            *(float4*)&dst[tx*4] = make_float4(vr[s8][0],vr[s8][1],vr[s8][2],vr[s8][3]);
            *(float4*)&dst[32+tx*4] = make_float4(vr[s8][4],vr[s8][5],vr[s8][6],vr[s8][7]);
        }
    } else {
#pragma unroll
        for (int c = 0; c < 8; c++) {
            int d = (c < 4) ? (tx*4 + c) : (32 + tx*4 + c - 4);
            float* dst = &Out[((size_t)bh*DEP + d)*SEQ + s0];
            *(float4*)&dst[0] = make_float4(vr[0][c],vr[1][c],vr[2][c],vr[3][c]);
            *(float4*)&dst[4] = make_float4(vr[4][c],vr[5][c],vr[6][c],vr[7][c]);
        }
    }
}

// =========================================================================
// Output GEMM: out[m,n] = Xgather[m,:] @ wo + bo.
// =========================================================================
__global__ __launch_bounds__(128)
void outproj_kernel(const float* __restrict__ W, const float* __restrict__ bias,
                    float* __restrict__ Out)
{
    __shared__ float As[16*132];
    __shared__ float Bs[16*68];
    const int t = threadIdx.x, tx = t & 7, ty = t >> 3;
    const int m0 = blockIdx.x * 128, n0 = blockIdx.y * 64;

    ull acc[4][8];
#pragma unroll
    for (int i = 0; i < 4; i++)
#pragma unroll
        for (int c = 0; c < 8; c++) acc[i][c] = 0ull;

    const int mA = m0 + t, bbA = mA >> 10, sA = mA & 1023;

    for (int kk = 0; kk < DM; kk += 16) {
#pragma unroll
        for (int j = 0; j < 4; j++) {
            int kb = kk + 4*j, hs = kb >> 6, dd = kb & 63;
            float4 v = *(const float4*)
                &g_X[(((size_t)bbA*HH + hs)*SEQ + sA)*DEP + dd];
            As[(4*j+0)*132 + t] = v.x; As[(4*j+1)*132 + t] = v.y;
            As[(4*j+2)*132 + t] = v.z; As[(4*j+3)*132 + t] = v.w;
        }
#pragma unroll
        for (int i = 0; i < 2; i++) {
            int idx = t + 128*i, bk = idx >> 4, bc = (idx & 15)*4;
            *(float4*)&Bs[bk*68 + bc] =
                *(const float4*)&W[(size_t)(kk+bk)*DM + n0 + bc];
        }
        __syncthreads();
#pragma unroll
        for (int k = 0; k < 16; k++) {
            ulonglong2 apA = *(const ulonglong2*)&As[k*132 + ty*8];
            ulonglong2 apB = *(const ulonglong2*)&As[k*132 + ty*8 + 4];
            float4 blo = *(const float4*)&Bs[k*68 + tx*4];
            float4 bhi = *(const float4*)&Bs[k*68 + 32 + tx*4];
            float bf[8] = {blo.x,blo.y,blo.z,blo.w,bhi.x,bhi.y,bhi.z,bhi.w};
#pragma unroll
            for (int c = 0; c < 8; c++) {
                ull bd = pk2(bf[c], bf[c]);
                fma2(acc[0][c], apA.x, bd); fma2(acc[1][c], apA.y, bd);
                fma2(acc[2][c], apB.x, bd); fma2(acc[3][c], apB.y, bd);
            }
        }
        __syncthreads();
    }

    float4 blo4 = *(const float4*)&bias[n0 + tx*4];
    float4 bhi4 = *(const float4*)&bias[n0 + 32 + tx*4];
#pragma unroll
    for (int rp = 0; rp < 4; rp++) {
        float2 fx[8];
#pragma unroll
        for (int c = 0; c < 8; c++) fx[c] = upk(acc[rp][c]);
#pragma unroll
        for (int e = 0; e < 2; e++) {
            int m = m0 + ty*8 + 2*rp + e;
            float a0=e?fx[0].y:fx[0].x, a1=e?fx[1].y:fx[1].x;
            float a2=e?fx[2].y:fx[2].x, a3=e?fx[3].y:fx[3].x;
            float a4=e?fx[4].y:fx[4].x, a5=e?fx[5].y:fx[5].x;
            float a6=e?fx[6].y:fx[6].x, a7=e?fx[7].y:fx[7].x;
            *(float4*)&Out[(size_t)m*DM + n0 + tx*4] =
                make_float4(a0+blo4.x, a1+blo4.y, a2+blo4.z, a3+blo4.w);
            *(float4*)&Out[(size_t)m*DM + n0 + 32 + tx*4] =
                make_float4(a4+bhi4.x, a5+bhi4.y, a6+bhi4.z, a7+bhi4.w);
        }
    }
}

// =========================================================================
// Attention (R7 structure; phase 1 rebuilt conflict-free from K^T tiles).
// One CTA per (b,h,16-q tile), 256 threads.  smem offsets as R7:
// Qpp[64][8] ull | Ms[1024] | KV tile (phase1 KtS[64][132], phase2 Vs[128][68])
// | Ss[16][1028]
// =========================================================================
#define KP   68
#define SP   1028
#define OFF_MS   1024
#define OFF_KS   2048
#define OFF_SS   (OFF_KS + 128*KP)
#define ATTN_SMEM_BYTES ((OFF_SS + 16*SP) * 4)

__global__ __launch_bounds__(256, 2)
void attn_kernel(const float* __restrict__ mask, const float* __restrict__ aw,
                 float* __restrict__ attn_out)
{
    extern __shared__ float sm[];
    ull*   Qpp = (ull*)sm;          // [d][qp]
    float* Ms  = sm + OFF_MS;
    float* Ks  = sm + OFF_KS;       // KtS pitch 132 (phase1) / V pitch 68 (phase2)
    float* Ss  = sm + OFF_SS;

    const int t = threadIdx.x, w = t >> 5, lane = t & 31;
    const int qt = blockIdx.x, h = blockIdx.y, b = blockIdx.z;
    const int bh = b*HH + h, q0 = qt*16;

    const float* Qg  = g_Q + ((size_t)bh*SEQ + q0)*DEP;
    const float* KTg = g_K + (size_t)bh*DEP*SEQ;
    const float* Vg  = g_V + (size_t)bh*SEQ*DEP;

    // Qpp[d*8+qp] = (Q[2qp][d], Q[2qp+1][d]); mask row
#pragma unroll
    for (int i = 0; i < 2; i++) {
        int idx = t + 256*i, d = idx >> 3, qp = idx & 7;
        Qpp[idx] = pk2(Qg[(2*qp)*DEP + d], Qg[(2*qp+1)*DEP + d]);
    }
    for (int i = t; i < SEQ; i += 256) Ms[i] = mask[(size_t)b*SEQ + i];

    // ---- phase 1: scores from K^T tiles (conflict-free) -----------------
    {
        const int qg = w & 3, half = w >> 2;
        const int qp0 = qg*2;            // q-pairs qp0, qp0+1 -> q rows 4qg..4qg+3
        const int krow = half*64 + lane;

        for (int kt = 0; kt < 8; kt++) {
            __syncthreads();
#pragma unroll
            for (int i = 0; i < 8; i++) {
                int lin = t + 256*i;
                int d = lin >> 5, c4 = (lin & 31)*4;
                *(float4*)&Ks[d*132 + c4] =
                    *(const float4*)&KTg[(size_t)d*SEQ + kt*128 + c4];
            }
            __syncthreads();

            ull a00=0ull, a01=0ull, a10=0ull, a11=0ull;
#pragma unroll 8
            for (int d = 0; d < DEP; d++) {
                float kv0 = Ks[d*132 + krow];
                float kv1 = Ks[d*132 + krow + 32];
                ulonglong2 qq = *(const ulonglong2*)&Qpp[d*8 + qp0];
                ull kd0 = pk2(kv0, kv0), kd1 = pk2(kv1, kv1);
                fma2(a00, kd0, qq.x); fma2(a01, kd1, qq.x);
                fma2(a10, kd0, qq.y); fma2(a11, kd1, qq.y);
            }
            int kk0 = kt*128 + krow;
            float2 f;
            f = upk(a00);
            Ss[(qg*4+0)*SP + kk0]      = f.x*0.125f;
            Ss[(qg*4+1)*SP + kk0]      = f.y*0.125f;
            f = upk(a01);
            Ss[(qg*4+0)*SP + kk0 + 32] = f.x*0.125f;
            Ss[(qg*4+1)*SP + kk0 + 32] = f.y*0.125f;
            f = upk(a10);
            Ss[(qg*4+2)*SP + kk0]      = f.x*0.125f;
            Ss[(qg*4+3)*SP + kk0]      = f.y*0.125f;
            f = upk(a11);
            Ss[(qg*4+2)*SP + kk0 + 32] = f.x*0.125f;
            Ss[(qg*4+3)*SP + kk0 + 32] = f.y*0.125f;
        }
    }
    __syncthreads();

    // ---- masked softmax + additional_weights (warp w: rows 2w, 2w+1) ----
#pragma unroll
    for (int rr = 0; rr < 2; rr++) {
        int r = 2*w + rr;
        float mx = -3.0e38f;
#pragma unroll
        for (int i = 0; i < 32; i++) {
            int k = lane + 32*i;
            float v = fmaf(Ms[k], -1.0e9f, Ss[r*SP + k]);
            Ss[r*SP + k] = v;
            mx = fmaxf(mx, v);
        }
#pragma unroll
        for (int off = 16; off > 0; off >>= 1)
            mx = fmaxf(mx, __shfl_xor_sync(0xffffffffu, mx, off));
        float sum = 0.f;
#pragma unroll
        for (int i = 0; i < 32; i++) {
            int k = lane + 32*i;
            float v = __expf(Ss[r*SP + k] - mx);
            Ss[r*SP + k] = v;
            sum += v;
        }
#pragma unroll
        for (int off = 16; off > 0; off >>= 1)
            sum += __shfl_xor_sync(0xffffffffu, sum, off);
        float inv = 1.0f / sum;
        const float* awr = aw + ((size_t)b*SEQ + q0 + r) * SEQ;
        float* ao = attn_out + ((size_t)bh*SEQ + q0 + r) * SEQ;
#pragma unroll
        for (int i = 0; i < 32; i++) {
            int k = lane + 32*i;
            float a = (Ss[r*SP + k] * inv) * awr[k];
            Ss[r*SP + k] = a;
            ao[k] = a;
        }
    }

    // ---- phase 2: X = A @ V  (verbatim R7) ------------------------------
    {
        const int qg2  = w & 3;
        const int half = w >> 2;
        const int qi   = lane >> 3;
        const int dg   = lane & 7;
        ull xa0=0ull, xa1=0ull, xb0=0ull, xb1=0ull;

        for (int vt = 0; vt < 8; vt++) {
            __syncthreads();
#pragma unroll
            for (int i = 0; i < 8; i++) {
                int lin = t + 256*i;
                int r = lin >> 4, c = (lin & 15)*4;
                *(float4*)&Ks[r*KP + c] =
                    *(const float4*)&Vg[(size_t)(vt*128 + r)*DEP + c];
            }
            __syncthreads();

            const float* arow = &Ss[(qg2*4 + qi)*SP + vt*128 + half*64];
#pragma unroll
            for (int j4 = 0; j4 < 16; j4++) {
                float4 a4 = *(const float4*)&arow[j4*4];
                float av[4] = {a4.x, a4.y, a4.z, a4.w};
#pragma unroll
                for (int j = 0; j < 4; j++) {
                    ull ad = pk2(av[j], av[j]);
                    int vr = half*64 + j4*4 + j;
                    ulonglong2 v1 = *(const ulonglong2*)&Ks[vr*KP + 4*dg];
                    ulonglong2 v2 = *(const ulonglong2*)&Ks[vr*KP + 32 + 4*dg];
                    fma2(xa0, v1.x, ad); fma2(xa1, v1.y, ad);
                    fma2(xb0, v2.x, ad); fma2(xb1, v2.y, ad);
                }
            }
        }

        float* Xp = sm;                       // overlaps Qpp+Ms (dead)
        ulonglong2 pa; pa.x = xa0; pa.y = xa1;
        ulonglong2 pb; pb.x = xb0; pb.y = xb1;
        *(ulonglong2*)&Xp[w*256 + qi*64 + 4*dg]      = pa;
        *(ulonglong2*)&Xp[w*256 + qi*64 + 32 + 4*dg] = pb;
    }
    __syncthreads();
    {
        float* Xp = sm;
        int q = t >> 4, c4 = (t & 15) * 4;
        int base = (q >> 2)*256 + (q & 3)*64 + c4;
        float4 u = *(float4*)&Xp[base];
        float4 v = *(float4*)&Xp[base + 4*256];
        *(float4*)&g_X[((size_t)bh*SEQ + q0 + q)*DEP + c4] =
            make_float4(u.x+v.x, u.y+v.y, u.z+v.z, u.w+v.w);
    }
}

// =========================================================================
extern "C" void kernel_launch(void* const* d_in, const int* in_sizes, int n_in,
                              void* d_out, int out_size)
{
    const float* q_in = (const float*)d_in[0];
    const float* k_in = (const float*)d_in[1];
    const float* v_in = (const float*)d_in[2];
    const float* mask = (const float*)d_in[3];
    const float* aw   = (const float*)d_in[4];
    const float* wq   = (const float*)d_in[5];
    const float* bq   = (const float*)d_in[6];
    const float* wk   = (const float*)d_in[7];
    const float* bk   = (const float*)d_in[8];
    const float* wv   = (const float*)d_in[9];
    const float* bv   = (const float*)d_in[10];
    const float* wo   = (const float*)d_in[11];
    const float* bo   = (const float*)d_in[12];

    float* out      = (float*)d_out;                // [B,S,512]
    float* attn_out = out + (size_t)BB*SEQ*DM;      // [B,H,S,S]

    float *Qp, *Kp, *Vp;
    cudaGetSymbolAddress((void**)&Qp, g_Q);
    cudaGetSymbolAddress((void**)&Kp, g_K);
    cudaGetSymbolAddress((void**)&Vp, g_V);

    dim3 gproj(64, 8);
    proj_kernel<<<gproj, 128>>>(q_in, wq, bq, Qp, 0);
    proj_kernel<<<gproj, 128>>>(k_in, wk, bk, Kp, 1);   // K transposed
    proj_kernel<<<gproj, 128>>>(v_in, wv, bv, Vp, 0);

    cudaFuncSetAttribute(attn_kernel,
                         cudaFuncAttributeMaxDynamicSharedMemorySize,
                         ATTN_SMEM_BYTES);
    attn_kernel<<<dim3(64, 8, 8), 256, ATTN_SMEM_BYTES>>>(mask, aw, attn_out);

    outproj_kernel<<<dim3(64, 8), 128>>>(wo, bo, out);
}

// round 13
// speedup vs baseline: 2.7298x; 1.2024x over previous
#include <cuda_runtime.h>
#include <math.h>

#define BB  8
#define HH  8
#define SEQ 1024
#define DM  512
#define DEP 64

__device__ float g_Q[BB*HH*SEQ*DEP];
__device__ float g_K[BB*HH*SEQ*DEP];   // TRANSPOSED: [bh][d][s]
__device__ float g_V[BB*HH*SEQ*DEP];
__device__ float g_X[BB*HH*SEQ*DEP];

typedef unsigned long long ull;
__device__ __forceinline__ ull pk2(float lo, float hi) {
    ull r; asm("mov.b64 %0, {%1, %2};" : "=l"(r) : "f"(lo), "f"(hi)); return r;
}
__device__ __forceinline__ void fma2(ull& d, ull a, ull b) {
    asm("fma.rn.f32x2 %0, %1, %2, %0;" : "+l"(d) : "l"(a), "l"(b));
}
__device__ __forceinline__ float2 upk(ull v) {
    float2 f; asm("mov.b64 {%0, %1}, %2;" : "=f"(f.x), "=f"(f.y) : "l"(v)); return f;
}

// =========================================================================
// Projection GEMM. tr=0: Out[bh][s][d].  tr=1: Out[bh][d][s] (K^T).
// =========================================================================
__global__ __launch_bounds__(128)
void proj_kernel(const float* __restrict__ X, const float* __restrict__ W,
                 const float* __restrict__ bias, float* __restrict__ Out, int tr)
{
    __shared__ float As[16*132];
    __shared__ float Bs[16*68];
    const int t = threadIdx.x, tx = t & 7, ty = t >> 3;
    const int m0 = blockIdx.x * 128, h = blockIdx.y, n0 = h*64;

    ull acc[4][8];
#pragma unroll
    for (int i = 0; i < 4; i++)
#pragma unroll
        for (int c = 0; c < 8; c++) acc[i][c] = 0ull;

    for (int kk = 0; kk < DM; kk += 16) {
#pragma unroll
        for (int j = 0; j < 4; j++) {
            float4 v = *(const float4*)&X[(size_t)(m0 + t)*DM + kk + 4*j];
            As[(4*j+0)*132 + t] = v.x; As[(4*j+1)*132 + t] = v.y;
            As[(4*j+2)*132 + t] = v.z; As[(4*j+3)*132 + t] = v.w;
        }
#pragma unroll
        for (int i = 0; i < 2; i++) {
            int idx = t + 128*i, bk = idx >> 4, bc = (idx & 15)*4;
            *(float4*)&Bs[bk*68 + bc] =
                *(const float4*)&W[(size_t)(kk+bk)*DM + n0 + bc];
        }
        __syncthreads();
#pragma unroll
        for (int k = 0; k < 16; k++) {
            ulonglong2 apA = *(const ulonglong2*)&As[k*132 + ty*8];
            ulonglong2 apB = *(const ulonglong2*)&As[k*132 + ty*8 + 4];
            float4 blo = *(const float4*)&Bs[k*68 + tx*4];
            float4 bhi = *(const float4*)&Bs[k*68 + 32 + tx*4];
            float bf[8] = {blo.x,blo.y,blo.z,blo.w,bhi.x,bhi.y,bhi.z,bhi.w};
#pragma unroll
            for (int c = 0; c < 8; c++) {
                ull bd = pk2(bf[c], bf[c]);
                fma2(acc[0][c], apA.x, bd); fma2(acc[1][c], apA.y, bd);
                fma2(acc[2][c], apB.x, bd); fma2(acc[3][c], apB.y, bd);
            }
        }
        __syncthreads();
    }

    float bf2[8];
    {
        float4 u = *(const float4*)&bias[n0 + tx*4];
        float4 v = *(const float4*)&bias[n0 + 32 + tx*4];
        bf2[0]=u.x; bf2[1]=u.y; bf2[2]=u.z; bf2[3]=u.w;
        bf2[4]=v.x; bf2[5]=v.y; bf2[6]=v.z; bf2[7]=v.w;
    }
    float vr[8][8];
#pragma unroll
    for (int rp = 0; rp < 4; rp++)
#pragma unroll
        for (int c = 0; c < 8; c++) {
            float2 f = upk(acc[rp][c]);
            vr[2*rp][c] = f.x + bf2[c]; vr[2*rp+1][c] = f.y + bf2[c];
        }

    const int bh = (m0 >> 10)*HH + h;
    const int s0 = (m0 & 1023) + ty*8;
    if (!tr) {
#pragma unroll
        for (int s8 = 0; s8 < 8; s8++) {
            float* dst = &Out[((size_t)bh*SEQ + s0 + s8)*DEP];
            *(float4*)&dst[tx*4] = make_float4(vr[s8][0],vr[s8][1],vr[s8][2],vr[s8][3]);
            *(float4*)&dst[32+tx*4] = make_float4(vr[s8][4],vr[s8][5],vr[s8][6],vr[s8][7]);
        }
    } else {
#pragma unroll
        for (int c = 0; c < 8; c++) {
            int d = (c < 4) ? (tx*4 + c) : (32 + tx*4 + c - 4);
            float* dst = &Out[((size_t)bh*DEP + d)*SEQ + s0];
            *(float4*)&dst[0] = make_float4(vr[0][c],vr[1][c],vr[2][c],vr[3][c]);
            *(float4*)&dst[4] = make_float4(vr[4][c],vr[5][c],vr[6][c],vr[7][c]);
        }
    }
}

// =========================================================================
// Output GEMM: out[m,n] = Xgather[m,:] @ wo + bo.
// =========================================================================
__global__ __launch_bounds__(128)
void outproj_kernel(const float* __restrict__ W, const float* __restrict__ bias,
                    float* __restrict__ Out)
{
    __shared__ float As[16*132];
    __shared__ float Bs[16*68];
    const int t = threadIdx.x, tx = t & 7, ty = t >> 3;
    const int m0 = blockIdx.x * 128, n0 = blockIdx.y * 64;

    ull acc[4][8];
#pragma unroll
    for (int i = 0; i < 4; i++)
#pragma unroll
        for (int c = 0; c < 8; c++) acc[i][c] = 0ull;

    const int mA = m0 + t, bbA = mA >> 10, sA = mA & 1023;

    for (int kk = 0; kk < DM; kk += 16) {
#pragma unroll
        for (int j = 0; j < 4; j++) {
            int kb = kk + 4*j, hs = kb >> 6, dd = kb & 63;
            float4 v = *(const float4*)
                &g_X[(((size_t)bbA*HH + hs)*SEQ + sA)*DEP + dd];
            As[(4*j+0)*132 + t] = v.x; As[(4*j+1)*132 + t] = v.y;
            As[(4*j+2)*132 + t] = v.z; As[(4*j+3)*132 + t] = v.w;
        }
#pragma unroll
        for (int i = 0; i < 2; i++) {
            int idx = t + 128*i, bk = idx >> 4, bc = (idx & 15)*4;
            *(float4*)&Bs[bk*68 + bc] =
                *(const float4*)&W[(size_t)(kk+bk)*DM + n0 + bc];
        }
        __syncthreads();
#pragma unroll
        for (int k = 0; k < 16; k++) {
            ulonglong2 apA = *(const ulonglong2*)&As[k*132 + ty*8];
            ulonglong2 apB = *(const ulonglong2*)&As[k*132 + ty*8 + 4];
            float4 blo = *(const float4*)&Bs[k*68 + tx*4];
            float4 bhi = *(const float4*)&Bs[k*68 + 32 + tx*4];
            float bf[8] = {blo.x,blo.y,blo.z,blo.w,bhi.x,bhi.y,bhi.z,bhi.w};
#pragma unroll
            for (int c = 0; c < 8; c++) {
                ull bd = pk2(bf[c], bf[c]);
                fma2(acc[0][c], apA.x, bd); fma2(acc[1][c], apA.y, bd);
                fma2(acc[2][c], apB.x, bd); fma2(acc[3][c], apB.y, bd);
            }
        }
        __syncthreads();
    }

    float4 blo4 = *(const float4*)&bias[n0 + tx*4];
    float4 bhi4 = *(const float4*)&bias[n0 + 32 + tx*4];
#pragma unroll
    for (int rp = 0; rp < 4; rp++) {
        float2 fx[8];
#pragma unroll
        for (int c = 0; c < 8; c++) fx[c] = upk(acc[rp][c]);
#pragma unroll
        for (int e = 0; e < 2; e++) {
            int m = m0 + ty*8 + 2*rp + e;
            float a0=e?fx[0].y:fx[0].x, a1=e?fx[1].y:fx[1].x;
            float a2=e?fx[2].y:fx[2].x, a3=e?fx[3].y:fx[3].x;
            float a4=e?fx[4].y:fx[4].x, a5=e?fx[5].y:fx[5].x;
            float a6=e?fx[6].y:fx[6].x, a7=e?fx[7].y:fx[7].x;
            *(float4*)&Out[(size_t)m*DM + n0 + tx*4] =
                make_float4(a0+blo4.x, a1+blo4.y, a2+blo4.z, a3+blo4.w);
            *(float4*)&Out[(size_t)m*DM + n0 + 32 + tx*4] =
                make_float4(a4+bhi4.x, a5+bhi4.y, a6+bhi4.z, a7+bhi4.w);
        }
    }
}

// =========================================================================
// Attention.  CTA per (b,h,16-q tile), 256 threads.
// Phase 1: warp = (q-half, k-quarter); lane = k column.  3 wf / 4 fma2,
//          all loads coalesced-unique or full-warp broadcast.
// Phase 2: warp = (d-half, k-quarter); lane = (q-group, d-group).
//          8 wf / 8 fma2 guaranteed; 4-way k partials reduced via smem.
// smem: Qpp[64][8] ull | Ms[1024] | Ks (K^T tile 64x132 / V 128x68 / Par)
//       | Ss[16][1029]
// =========================================================================
#define KP   68
#define SP   1029
#define OFF_MS   1024
#define OFF_KS   2048
#define OFF_SS   (OFF_KS + 128*KP)
#define ATTN_SMEM_BYTES ((OFF_SS + 16*SP) * 4)

__global__ __launch_bounds__(256, 2)
void attn_kernel(const float* __restrict__ mask, const float* __restrict__ aw,
                 float* __restrict__ attn_out)
{
    extern __shared__ float sm[];
    ull*   Qpp = (ull*)sm;          // [d][qp]
    float* Ms  = sm + OFF_MS;
    float* Ks  = sm + OFF_KS;       // KtS pitch 132 (ph1) / V pitch 68 (ph2) / Par
    float* Ss  = sm + OFF_SS;

    const int t = threadIdx.x, w = t >> 5, lane = t & 31;
    const int qt = blockIdx.x, h = blockIdx.y, b = blockIdx.z;
    const int bh = b*HH + h, q0 = qt*16;

    const float* Qg  = g_Q + ((size_t)bh*SEQ + q0)*DEP;
    const float* KTg = g_K + (size_t)bh*DEP*SEQ;
    const float* Vg  = g_V + (size_t)bh*SEQ*DEP;

    // Qpp[d*8+qp] = (Q[2qp][d], Q[2qp+1][d]); mask row
#pragma unroll
    for (int i = 0; i < 2; i++) {
        int idx = t + 256*i, d = idx >> 3, qp = idx & 7;
        Qpp[idx] = pk2(Qg[(2*qp)*DEP + d], Qg[(2*qp+1)*DEP + d]);
    }
    for (int i = t; i < SEQ; i += 256) Ms[i] = mask[(size_t)b*SEQ + i];

    // ---- phase 1: scores ------------------------------------------------
    {
        const int qh = w & 1;            // q rows 8qh..8qh+7 (qpairs 4qh..4qh+3)
        const int kq = w >> 1;           // k-quarter within tile
        const int kcol = kq*32 + lane;   // within-tile k column

        for (int kt = 0; kt < 8; kt++) {
            __syncthreads();
#pragma unroll
            for (int i = 0; i < 8; i++) {
                int lin = t + 256*i;
                int d = lin >> 5, c4 = (lin & 31)*4;
                *(float4*)&Ks[d*132 + c4] =
                    *(const float4*)&KTg[(size_t)d*SEQ + kt*128 + c4];
            }
            __syncthreads();

            ull a0=0ull, a1=0ull, a2=0ull, a3=0ull;
#pragma unroll 8
            for (int d = 0; d < DEP; d++) {
                float kv = Ks[d*132 + kcol];          // coalesced, unique
                ull kd = pk2(kv, kv);
                ulonglong2 qA = *(const ulonglong2*)&Qpp[d*8 + 4*qh];     // bcast
                ulonglong2 qB = *(const ulonglong2*)&Qpp[d*8 + 4*qh + 2]; // bcast
                fma2(a0, kd, qA.x); fma2(a1, kd, qA.y);
                fma2(a2, kd, qB.x); fma2(a3, kd, qB.y);
            }
            int kk = kt*128 + kcol;
            float2 f;
            f = upk(a0); Ss[(8*qh+0)*SP + kk] = f.x*0.125f;
                         Ss[(8*qh+1)*SP + kk] = f.y*0.125f;
            f = upk(a1); Ss[(8*qh+2)*SP + kk] = f.x*0.125f;
                         Ss[(8*qh+3)*SP + kk] = f.y*0.125f;
            f = upk(a2); Ss[(8*qh+4)*SP + kk] = f.x*0.125f;
                         Ss[(8*qh+5)*SP + kk] = f.y*0.125f;
            f = upk(a3); Ss[(8*qh+6)*SP + kk] = f.x*0.125f;
                         Ss[(8*qh+7)*SP + kk] = f.y*0.125f;
        }
    }
    __syncthreads();

    // ---- masked softmax + additional_weights (warp w: rows 2w, 2w+1) ----
#pragma unroll
    for (int rr = 0; rr < 2; rr++) {
        int r = 2*w + rr;
        float mx = -3.0e38f;
#pragma unroll
        for (int i = 0; i < 32; i++) {
            int k = lane + 32*i;
            float v = fmaf(Ms[k], -1.0e9f, Ss[r*SP + k]);
            Ss[r*SP + k] = v;
            mx = fmaxf(mx, v);
        }
#pragma unroll
        for (int off = 16; off > 0; off >>= 1)
            mx = fmaxf(mx, __shfl_xor_sync(0xffffffffu, mx, off));
        float sum = 0.f;
#pragma unroll
        for (int i = 0; i < 32; i++) {
            int k = lane + 32*i;
            float v = __expf(Ss[r*SP + k] - mx);
            Ss[r*SP + k] = v;
            sum += v;
        }
#pragma unroll
        for (int off = 16; off > 0; off >>= 1)
            sum += __shfl_xor_sync(0xffffffffu, sum, off);
        float inv = 1.0f / sum;
        const float* awr = aw + ((size_t)b*SEQ + q0 + r) * SEQ;
        float* ao = attn_out + ((size_t)bh*SEQ + q0 + r) * SEQ;
#pragma unroll
        for (int i = 0; i < 32; i++) {
            int k = lane + 32*i;
            float a = (Ss[r*SP + k] * inv) * awr[k];
            Ss[r*SP + k] = a;
            ao[k] = a;
        }
    }

    // ---- phase 2: X = A @ V  (4-way k-split partials) -------------------
    {
        const int dh = w & 1;            // d-half
        const int kq = w >> 1;           // k-quarter
        const int qg = lane >> 3;        // q rows 4qg..4qg+3
        const int dg = lane & 7;         // d = 32dh + 4dg .. +3
        const int dcol = 32*dh + 4*dg;

        ull x[4][2];
#pragma unroll
        for (int qi = 0; qi < 4; qi++) { x[qi][0] = 0ull; x[qi][1] = 0ull; }

        for (int vt = 0; vt < 8; vt++) {
            __syncthreads();
#pragma unroll
            for (int i = 0; i < 8; i++) {
                int lin = t + 256*i;
                int r = lin >> 4, c = (lin & 15)*4;
                *(float4*)&Ks[r*KP + c] =
                    *(const float4*)&Vg[(size_t)(vt*128 + r)*DEP + c];
            }
            __syncthreads();

            const int kbase = vt*128 + kq*32;
#pragma unroll 4
            for (int ki = 0; ki < 32; ki++) {
                int k = kbase + ki;
                ulonglong2 vv =
                    *(const ulonglong2*)&Ks[(kq*32 + ki)*KP + dcol];  // contig 128B
#pragma unroll
                for (int qi = 0; qi < 4; qi++) {
                    float a = Ss[(4*qg + qi)*SP + k];                 // word bcast
                    ull ad = pk2(a, a);
                    fma2(x[qi][0], vv.x, ad);
                    fma2(x[qi][1], vv.y, ad);
                }
            }
        }
        __syncthreads();

        // partials -> Par (reuses Ks region; V tile dead)
        float* Par = Ks;                 // [8 warps][16 q][32 d]
#pragma unroll
        for (int qi = 0; qi < 4; qi++) {
            float2 f0 = upk(x[qi][0]), f1 = upk(x[qi][1]);
            *(float2*)&Par[w*512 + (4*qg + qi)*32 + 4*dg]     = make_float2(f0.x, f0.y);
            *(float2*)&Par[w*512 + (4*qg + qi)*32 + 4*dg + 2] = make_float2(f1.x, f1.y);
        }
    }
    __syncthreads();
    {
        float* Par = Ks;
        int q = t >> 4, c4 = (t & 15)*4;
        int dh = c4 >> 5, dc = c4 & 31;
        float4 s = make_float4(0.f, 0.f, 0.f, 0.f);
#pragma unroll
        for (int kq = 0; kq < 4; kq++) {
            float4 u = *(float4*)&Par[(2*kq + dh)*512 + q*32 + dc];
            s.x += u.x; s.y += u.y; s.z += u.z; s.w += u.w;
        }
        *(float4*)&g_X[((size_t)bh*SEQ + q0 + q)*DEP + c4] = s;
    }
}

// =========================================================================
extern "C" void kernel_launch(void* const* d_in, const int* in_sizes, int n_in,
                              void* d_out, int out_size)
{
    const float* q_in = (const float*)d_in[0];
    const float* k_in = (const float*)d_in[1];
    const float* v_in = (const float*)d_in[2];
    const float* mask = (const float*)d_in[3];
    const float* aw   = (const float*)d_in[4];
    const float* wq   = (const float*)d_in[5];
    const float* bq   = (const float*)d_in[6];
    const float* wk   = (const float*)d_in[7];
    const float* bk   = (const float*)d_in[8];
    const float* wv   = (const float*)d_in[9];
    const float* bv   = (const float*)d_in[10];
    const float* wo   = (const float*)d_in[11];
    const float* bo   = (const float*)d_in[12];

    float* out      = (float*)d_out;                // [B,S,512]
    float* attn_out = out + (size_t)BB*SEQ*DM;      // [B,H,S,S]

    float *Qp, *Kp, *Vp;
    cudaGetSymbolAddress((void**)&Qp, g_Q);
    cudaGetSymbolAddress((void**)&Kp, g_K);
    cudaGetSymbolAddress((void**)&Vp, g_V);

    dim3 gproj(64, 8);
    proj_kernel<<<gproj, 128>>>(q_in, wq, bq, Qp, 0);
    proj_kernel<<<gproj, 128>>>(k_in, wk, bk, Kp, 1);   // K transposed
    proj_kernel<<<gproj, 128>>>(v_in, wv, bv, Vp, 0);

    cudaFuncSetAttribute(attn_kernel,
                         cudaFuncAttributeMaxDynamicSharedMemorySize,
                         ATTN_SMEM_BYTES);
    attn_kernel<<<dim3(64, 8, 8), 256, ATTN_SMEM_BYTES>>>(mask, aw, attn_out);

    outproj_kernel<<<dim3(64, 8), 128>>>(wo, bo, out);
}